// round 14
// baseline (speedup 1.0000x reference)
#include <cuda_runtime.h>

#define EDGES   65536
#define EHALF   32768          // edges per scan half
#define NODESN  2048
#define DI      64
#define DOUT    64
#define EPSV    1e-6f
#define RCHUNK  16             // rows per scan tile (4096 tiles per half)
#define CAP     256            // adjacency capacity per node

// scratch (no cudaMalloc allowed)
__device__ int    g_si[EDGES];          // src index per edge
__device__ int    g_ti[EDGES];          // tgt index per edge
__device__ int    g_cnt[NODESN];        // per-target edge count (reset by final gather)
__device__ int    g_done[NODESN];       // slots consumed by partial gather
__device__ int    g_adj[NODESN * CAP];  // per-target SOURCE-NODE lists
__device__ float  g_P[NODESN * DOUT];   // x @ Wf_top
__device__ float  g_Q[NODESN * DOUT];   // x @ Wf_bot
__device__ float  g_eu[NODESN];         // exp(x . Ww_top)
__device__ float  g_v[NODESN];          // x . Ww_bot
__device__ float2 g_pacc[NODESN * 32];  // partial numerator (per node per lane)
__device__ float  g_pasum[NODESN];      // partial denominator

// ---------------------------------------------------------------------------
// K0 (k_pre): per-node projections P,Q,exp(u),v. Side stream, fully
// overlapped with scan half 0.
// ---------------------------------------------------------------------------
__global__ void __launch_bounds__(256) k_pre(const float* __restrict__ x,
                                             const float* __restrict__ Wf,
                                             const float* __restrict__ Ww) {
    __shared__ float sW[2 * DI * DOUT];   // 32 KB
    __shared__ float sx[DI * 64];         // 16 KB, transposed x tile

    const int tid = threadIdx.x;
    const int n0 = blockIdx.x * 64;

    {
        const float4* Wf4 = (const float4*)Wf;
        float4* sW4 = (float4*)sW;
#pragma unroll
        for (int i = 0; i < 8; ++i)
            sW4[tid + i * 256] = Wf4[tid + i * 256];
    }
    {
        const float4* x4 = (const float4*)x;
#pragma unroll
        for (int i = 0; i < 4; ++i) {
            int idx = tid + i * 256;
            int nl = idx >> 4;
            int kq = idx & 15;
            float4 vv = x4[(n0 + nl) * (DI / 4) + kq];
            sx[(kq * 4 + 0) * 64 + nl] = vv.x;
            sx[(kq * 4 + 1) * 64 + nl] = vv.y;
            sx[(kq * 4 + 2) * 64 + nl] = vv.z;
            sx[(kq * 4 + 3) * 64 + nl] = vv.w;
        }
    }
    __syncthreads();

    const int nl = tid >> 2;
    const int dg = (tid & 3) * 16;

    float accP[16] = {}, accQ[16] = {};
    const float4* sW4 = (const float4*)sW;
#pragma unroll 4
    for (int k = 0; k < DI; ++k) {
        float xv = sx[k * 64 + nl];
        int bP = (k * DOUT + dg) >> 2;
        int bQ = ((DI + k) * DOUT + dg) >> 2;
#pragma unroll
        for (int j = 0; j < 4; ++j) {
            float4 w = sW4[bP + j];
            accP[j * 4 + 0] += xv * w.x; accP[j * 4 + 1] += xv * w.y;
            accP[j * 4 + 2] += xv * w.z; accP[j * 4 + 3] += xv * w.w;
            float4 q = sW4[bQ + j];
            accQ[j * 4 + 0] += xv * q.x; accQ[j * 4 + 1] += xv * q.y;
            accQ[j * 4 + 2] += xv * q.z; accQ[j * 4 + 3] += xv * q.w;
        }
    }
    float4* P4 = (float4*)(g_P + (n0 + nl) * DOUT + dg);
    float4* Q4 = (float4*)(g_Q + (n0 + nl) * DOUT + dg);
#pragma unroll
    for (int j = 0; j < 4; ++j) {
        P4[j] = make_float4(accP[j*4+0], accP[j*4+1], accP[j*4+2], accP[j*4+3]);
        Q4[j] = make_float4(accQ[j*4+0], accQ[j*4+1], accQ[j*4+2], accQ[j*4+3]);
    }

    if (tid < 64) {
        float uu = 0.f, vv = 0.f;
#pragma unroll 8
        for (int k = 0; k < DI; ++k) {
            float xv = sx[k * 64 + tid];
            uu += xv * __ldg(&Ww[k]);
            vv += xv * __ldg(&Ww[DI + k]);
        }
        g_eu[n0 + tid] = expf(uu);
        g_v[n0 + tid]  = vv;
    }
}

// ---------------------------------------------------------------------------
// K1 (k_scan_half): fused streaming scan over HALF the edge columns.
// Same two-accumulator R6 pattern; grid (32, 128) = 4096 tiles of 16 rows.
// g4base selects the column half (0 or 8192 float4 groups).
// ---------------------------------------------------------------------------
__global__ void __launch_bounds__(256) k_scan_half(const float4* __restrict__ src4,
                                                   const float4* __restrict__ tgt4,
                                                   int g4base) {
    const int g4 = g4base + blockIdx.x * blockDim.x + threadIdx.x;
    const int r0 = blockIdx.y * RCHUNK;
    const int stride4 = EDGES / 4;                          // 16384
    size_t base = (size_t)r0 * stride4 + g4;

    float4 ws = {0.f,0.f,0.f,0.f}, wt = {0.f,0.f,0.f,0.f};  // sum n*v
    float4 ps = {0.f,0.f,0.f,0.f}, pt = {0.f,0.f,0.f,0.f};  // sum v

#pragma unroll 8
    for (int n = 0; n < RCHUNK; ++n) {
        float fn = (float)(r0 + n);
        float4 vs = __ldcs(&src4[base]);
        float4 vt = __ldcs(&tgt4[base]);
        base += stride4;
        ws.x += vs.x * fn; ws.y += vs.y * fn; ws.z += vs.z * fn; ws.w += vs.w * fn;
        ps.x += vs.x;      ps.y += vs.y;      ps.z += vs.z;      ps.w += vs.w;
        wt.x += vt.x * fn; wt.y += vt.y * fn; wt.z += vt.z * fn; wt.w += vt.w * fn;
        pt.x += vt.x;      pt.y += vt.y;      pt.z += vt.z;      pt.w += vt.w;
    }
    int e0 = g4 * 4;
    if (ps.x > 0.5f) g_si[e0 + 0] = (int)(ws.x + 0.5f);
    if (ps.y > 0.5f) g_si[e0 + 1] = (int)(ws.y + 0.5f);
    if (ps.z > 0.5f) g_si[e0 + 2] = (int)(ws.z + 0.5f);
    if (ps.w > 0.5f) g_si[e0 + 3] = (int)(ws.w + 0.5f);
    if (pt.x > 0.5f) g_ti[e0 + 0] = (int)(wt.x + 0.5f);
    if (pt.y > 0.5f) g_ti[e0 + 1] = (int)(wt.y + 0.5f);
    if (pt.z > 0.5f) g_ti[e0 + 2] = (int)(wt.z + 0.5f);
    if (pt.w > 0.5f) g_ti[e0 + 3] = (int)(wt.w + 0.5f);
}

// ---------------------------------------------------------------------------
// K2 (k_build_range): append [e0base, e0base+EHALF) to target adjacency,
// storing the SOURCE node id. Counters continue across the two calls.
// ---------------------------------------------------------------------------
__global__ void __launch_bounds__(256) k_build_range(int e0base) {
    int e = e0base + blockIdx.x * blockDim.x + threadIdx.x;
    int t = g_ti[e];
    int s = g_si[e];
    int slot = atomicAdd(&g_cnt[t], 1);
    g_adj[t * CAP + slot] = s;
}

// ---------------------------------------------------------------------------
// K3 (k_gather_part): partial gather over adjacency built so far (half 0).
// Runs on the side stream, overlapped with scan half 1. Block = node,
// 8 warps stride the list; block-reduced partials go to g_pacc/g_pasum;
// the consumed count is snapshotted in g_done.
// ---------------------------------------------------------------------------
__global__ void __launch_bounds__(256) k_gather_part(const float* __restrict__ bf,
                                                     const float* __restrict__ bw) {
    __shared__ float2 sacc[8][32];
    __shared__ float  sasum[8];

    const int warp = threadIdx.x >> 5;
    const int lane = threadIdx.x & 31;
    const int t    = blockIdx.x;
    const int cnt0 = g_cnt[t];

    const int* adj = g_adj + t * CAP;
    const float2* P2 = (const float2*)g_P;

    float2 q = ((const float2*)g_Q)[t * 32 + lane];
    float2 b = __ldg(&((const float2*)bf)[lane]);
    const float c = q.x + b.x;
    const float d = q.y + b.y;

    float2 acc = make_float2(0.f, 0.f);
    float  asum = 0.f;
    for (int k = warp; k < cnt0; k += 8) {
        int s = adj[k];
        float a = g_eu[s];
        float2 p = P2[s * 32 + lane];
        acc.x += a * fmaxf(p.x + c, 0.f);
        acc.y += a * fmaxf(p.y + d, 0.f);
        asum  += a;
    }
    sacc[warp][lane] = acc;
    if (lane == 0) sasum[warp] = asum;
    __syncthreads();

    if (warp == 0) {
        float ax = 0.f, ay = 0.f, as = 0.f;
#pragma unroll
        for (int wb = 0; wb < 8; ++wb) {
            float2 a = sacc[wb][lane];
            ax += a.x; ay += a.y; as += sasum[wb];
        }
        g_pacc[t * 32 + lane] = make_float2(ax, ay);
        if (lane == 0) { g_pasum[t] = as; g_done[t] = cnt0; }
    }
}

// ---------------------------------------------------------------------------
// K4 (k_gather_fin): gather the remaining slots [g_done[t], g_cnt[t]),
// combine with saved partials, normalize, write out. Resets g_cnt.
// evt factored out of the softmax ratio (exact except eps).
// ---------------------------------------------------------------------------
__global__ void __launch_bounds__(256) k_gather_fin(const float* __restrict__ bf,
                                                    const float* __restrict__ bw,
                                                    float* __restrict__ out) {
    __shared__ float2 sacc[8][32];
    __shared__ float  sasum[8];

    const int warp = threadIdx.x >> 5;
    const int lane = threadIdx.x & 31;
    const int t    = blockIdx.x;
    const int done = g_done[t];
    const int deg  = g_cnt[t];

    const int* adj = g_adj + t * CAP;
    const float2* P2 = (const float2*)g_P;

    float2 q = ((const float2*)g_Q)[t * 32 + lane];
    float2 b = __ldg(&((const float2*)bf)[lane]);
    const float c = q.x + b.x;
    const float d = q.y + b.y;

    float2 acc = make_float2(0.f, 0.f);
    float  asum = 0.f;
    for (int k = done + warp; k < deg; k += 8) {
        int s = adj[k];
        float a = g_eu[s];
        float2 p = P2[s * 32 + lane];
        acc.x += a * fmaxf(p.x + c, 0.f);
        acc.y += a * fmaxf(p.y + d, 0.f);
        asum  += a;
    }
    sacc[warp][lane] = acc;
    if (lane == 0) sasum[warp] = asum;
    __syncthreads();

    if (warp == 0) {
        float ax = 0.f, ay = 0.f, as = 0.f;
#pragma unroll
        for (int wb = 0; wb < 8; ++wb) {
            float2 a = sacc[wb][lane];
            ax += a.x; ay += a.y; as += sasum[wb];
        }
        float2 pa = g_pacc[t * 32 + lane];
        ax += pa.x; ay += pa.y; as += g_pasum[t];
        const float evt = expf(g_v[t] + __ldg(bw));
        float inv = evt / (evt * as + EPSV);
        ((float2*)out)[t * 32 + lane] = make_float2(ax * inv, ay * inv);
        if (lane == 0) g_cnt[t] = 0;           // self-clean for next replay
    }
}

// ---------------------------------------------------------------------------
extern "C" void kernel_launch(void* const* d_in, const int* in_sizes, int n_in,
                              void* d_out, int out_size) {
    const float* x   = (const float*)d_in[0];
    const float* src = (const float*)d_in[1];
    const float* tgt = (const float*)d_in[2];
    const float* Wf  = (const float*)d_in[3];
    const float* bf  = (const float*)d_in[4];
    const float* Ww  = (const float*)d_in[5];
    const float* bw  = (const float*)d_in[6];
    float* out = (float*)d_out;

    // side stream + events, created once on the (uncaptured) first call
    static cudaStream_t s2 = nullptr;
    static cudaEvent_t ev_fork = nullptr, ev_h0 = nullptr, ev_side = nullptr;
    if (s2 == nullptr) {
        cudaStreamCreateWithFlags(&s2, cudaStreamNonBlocking);
        cudaEventCreateWithFlags(&ev_fork, cudaEventDisableTiming);
        cudaEventCreateWithFlags(&ev_h0,   cudaEventDisableTiming);
        cudaEventCreateWithFlags(&ev_side, cudaEventDisableTiming);
    }

    const dim3 sgrid(EHALF / 4 / 256, NODESN / RCHUNK);   // (32, 128)

    // fork: k_pre overlaps scan half 0
    cudaEventRecord(ev_fork, 0);
    cudaStreamWaitEvent(s2, ev_fork, 0);
    k_pre<<<NODESN / 64, 256, 0, s2>>>(x, Wf, Ww);

    // main: scan half 0 (columns 0..32767)
    k_scan_half<<<sgrid, 256>>>((const float4*)src, (const float4*)tgt, 0);
    cudaEventRecord(ev_h0, 0);

    // side: build + partial gather over half-0 edges, overlapped with half 1
    cudaStreamWaitEvent(s2, ev_h0, 0);
    k_build_range<<<EHALF / 256, 256, 0, s2>>>(0);
    k_gather_part<<<NODESN, 256, 0, s2>>>(bf, bw);
    cudaEventRecord(ev_side, s2);

    // main: scan half 1 (columns 32768..65535)
    k_scan_half<<<sgrid, 256>>>((const float4*)src, (const float4*)tgt,
                                EHALF / 4);

    // main: finish — build half-1 edges, gather remainder + combine
    cudaStreamWaitEvent(0, ev_side, 0);
    k_build_range<<<EHALF / 256, 256>>>(EHALF);
    k_gather_fin<<<NODESN, 256>>>(bf, bw, out);
}